// round 1
// baseline (speedup 1.0000x reference)
#include <cuda_runtime.h>
#include <cstdint>

#define N_NODES 100000
#define N_EDGES 3200000
#define DIM     256

// Scratch for Y = X @ W^T  (102.4 MB). Static __device__ array: no allocation.
__device__ float g_Y[(size_t)N_NODES * DIM];

// ---------------------------------------------------------------------------
// Kernel 1: out[m, :] = b[:]   (output poisoned by harness; init with bias)
// ---------------------------------------------------------------------------
__global__ void __launch_bounds__(256) init_out_kernel(const float* __restrict__ b,
                                                       float* __restrict__ out) {
    int i = blockIdx.x * blockDim.x + threadIdx.x;     // index over float4s
    const int total = N_NODES * (DIM / 4);
    if (i < total) {
        float4 bv = reinterpret_cast<const float4*>(b)[i & (DIM / 4 - 1)];
        reinterpret_cast<float4*>(out)[i] = bv;
    }
}

// ---------------------------------------------------------------------------
// Kernel 2: Y = X @ W^T   (M=100000, N=256, K=256, all fp32, NT layout)
// Block tile 128x64, K-tile 16, 256 threads, 8x4 outputs/thread.
// ---------------------------------------------------------------------------
#define BM 128
#define BN 64
#define BK 16
#define TM 8
#define TN 4

__global__ void __launch_bounds__(256) gemm_xwt_kernel(const float* __restrict__ X,
                                                       const float* __restrict__ W,
                                                       int M) {
    __shared__ float Xs[BK][BM + 4];   // +4 keeps rows 16B-aligned for float4 reads
    __shared__ float Ws[BK][BN + 4];

    const int bm0 = blockIdx.y * BM;
    const int bn0 = blockIdx.x * BN;
    const int tid = threadIdx.x;
    const int tx  = tid & 15;          // N direction: 16 * TN = 64
    const int ty  = tid >> 4;          // M direction: 16 * TM = 128

    float acc[TM][TN];
#pragma unroll
    for (int m = 0; m < TM; m++)
#pragma unroll
        for (int n = 0; n < TN; n++) acc[m][n] = 0.0f;

    for (int kk = 0; kk < DIM; kk += BK) {
        // Load X tile: 128 rows x 16 k = 512 float4, 2 per thread
#pragma unroll
        for (int j = 0; j < 2; j++) {
            int i  = tid + 256 * j;
            int r  = i >> 2;           // 0..127
            int kq = i & 3;            // 0..3 (float4 within k-chunk)
            int gm = bm0 + r;
            float4 v = make_float4(0.f, 0.f, 0.f, 0.f);
            if (gm < M)
                v = *reinterpret_cast<const float4*>(X + (size_t)gm * DIM + kk + kq * 4);
            Xs[kq * 4 + 0][r] = v.x;
            Xs[kq * 4 + 1][r] = v.y;
            Xs[kq * 4 + 2][r] = v.z;
            Xs[kq * 4 + 3][r] = v.w;
        }
        // Load W tile: 64 rows x 16 k = 256 float4, 1 per thread
        {
            int r  = tid >> 2;         // 0..63
            int kq = tid & 3;
            float4 v = *reinterpret_cast<const float4*>(W + (size_t)(bn0 + r) * DIM + kk + kq * 4);
            Ws[kq * 4 + 0][r] = v.x;
            Ws[kq * 4 + 1][r] = v.y;
            Ws[kq * 4 + 2][r] = v.z;
            Ws[kq * 4 + 3][r] = v.w;
        }
        __syncthreads();

#pragma unroll
        for (int k = 0; k < BK; k++) {
            const float4* xr = reinterpret_cast<const float4*>(&Xs[k][ty * TM]);
            float4 a0 = xr[0];
            float4 a1 = xr[1];
            const float4* wr = reinterpret_cast<const float4*>(&Ws[k][tx * TN]);
            float4 bb = wr[0];
            float a[TM] = {a0.x, a0.y, a0.z, a0.w, a1.x, a1.y, a1.z, a1.w};
            float bv[TN] = {bb.x, bb.y, bb.z, bb.w};
#pragma unroll
            for (int m = 0; m < TM; m++)
#pragma unroll
                for (int n = 0; n < TN; n++)
                    acc[m][n] = fmaf(a[m], bv[n], acc[m][n]);
        }
        __syncthreads();
    }

    // Write Y (vectorized: TN=4 contiguous floats per row)
#pragma unroll
    for (int m = 0; m < TM; m++) {
        int gm = bm0 + ty * TM + m;
        if (gm < M) {
            float4 v = make_float4(acc[m][0], acc[m][1], acc[m][2], acc[m][3]);
            *reinterpret_cast<float4*>(g_Y + (size_t)gm * DIM + bn0 + tx * TN) = v;
        }
    }
}

// ---------------------------------------------------------------------------
// Kernel 3: scatter-reduce.  One warp per edge:
//   out[row[e], :] += val[e] * Y[col[e], :]
// Each lane handles 8 floats (2x float4) -> 2 red.global.add.v4.f32 per lane.
// ---------------------------------------------------------------------------
__device__ __forceinline__ void red_add_v4(float* addr, float4 v) {
    asm volatile("red.global.add.v4.f32 [%0], {%1, %2, %3, %4};"
                 :: "l"(addr), "f"(v.x), "f"(v.y), "f"(v.z), "f"(v.w)
                 : "memory");
}

__global__ void __launch_bounds__(256) spmm_scatter_kernel(const int* __restrict__ erow,
                                                           const int* __restrict__ ecol,
                                                           const float* __restrict__ eval,
                                                           float* __restrict__ out) {
    int warp = (blockIdx.x * blockDim.x + threadIdx.x) >> 5;
    int lane = threadIdx.x & 31;
    if (warp >= N_EDGES) return;

    const int   r = erow[warp];
    const int   c = ecol[warp];
    const float v = eval[warp];

    const float4* src = reinterpret_cast<const float4*>(g_Y + (size_t)c * DIM);
    float4 a0 = src[lane];
    float4 a1 = src[lane + 32];

    a0.x *= v; a0.y *= v; a0.z *= v; a0.w *= v;
    a1.x *= v; a1.y *= v; a1.z *= v; a1.w *= v;

    float* dst = out + (size_t)r * DIM;
    red_add_v4(dst + lane * 4,       a0);
    red_add_v4(dst + lane * 4 + 128, a1);
}

// ---------------------------------------------------------------------------
// Launch: inputs in metadata order: X, edge_row, edge_col, edge_val, W, b
// ---------------------------------------------------------------------------
extern "C" void kernel_launch(void* const* d_in, const int* in_sizes, int n_in,
                              void* d_out, int out_size) {
    const float* X    = (const float*)d_in[0];
    const int*   erow = (const int*)  d_in[1];
    const int*   ecol = (const int*)  d_in[2];
    const float* eval = (const float*)d_in[3];
    const float* W    = (const float*)d_in[4];
    const float* b    = (const float*)d_in[5];
    float*       out  = (float*)d_out;

    // 1) out = broadcast(b)
    {
        int total  = N_NODES * (DIM / 4);
        int blocks = (total + 255) / 256;
        init_out_kernel<<<blocks, 256>>>(b, out);
    }
    // 2) Y = X @ W^T
    {
        dim3 grid(DIM / BN, (N_NODES + BM - 1) / BM);
        gemm_xwt_kernel<<<grid, 256>>>(X, W, N_NODES);
    }
    // 3) out += segment_sum(val * Y[col]) via vector reductions
    {
        int warps_per_block = 256 / 32;
        int blocks = (N_EDGES + warps_per_block - 1) / warps_per_block;
        spmm_scatter_kernel<<<blocks, 256>>>(erow, ecol, eval, out);
    }
}

// round 3
// speedup vs baseline: 1.5260x; 1.5260x over previous
#include <cuda_runtime.h>
#include <cstdint>

#define N_NODES 100000
#define N_EDGES 3200000
#define DIM     256

// ---------------------------------------------------------------------------
// Static device scratch (no runtime allocation allowed)
// ---------------------------------------------------------------------------
__device__ float g_Y[(size_t)N_NODES * DIM];     // X @ W^T          (102.4 MB)
__device__ int   g_colS[N_EDGES];                // sorted edge cols ( 12.8 MB)
__device__ float g_valS[N_EDGES];                // sorted edge vals ( 12.8 MB)
__device__ int   g_cnt[N_NODES];                 // per-row degree
__device__ int   g_off[N_NODES];                 // exclusive prefix of cnt
__device__ int   g_cur[N_NODES];                 // scatter cursor

// ---------------------------------------------------------------------------
// Kernel A: zero counters + cursors
// ---------------------------------------------------------------------------
__global__ void __launch_bounds__(256) zero_kernel() {
    int i = blockIdx.x * blockDim.x + threadIdx.x;
    if (i < N_NODES) { g_cnt[i] = 0; g_cur[i] = 0; }
}

// ---------------------------------------------------------------------------
// Kernel B: histogram of edge destination rows
// ---------------------------------------------------------------------------
__global__ void __launch_bounds__(256) hist_kernel(const int* __restrict__ erow) {
    int i = blockIdx.x * blockDim.x + threadIdx.x;
    if (i < N_EDGES) atomicAdd(&g_cnt[erow[i]], 1);
}

// ---------------------------------------------------------------------------
// Kernel C: single-block chunked exclusive scan of g_cnt -> g_off
// 1024 threads; each owns a contiguous chunk of ~98 counters.
// ---------------------------------------------------------------------------
#define SCAN_THREADS 1024
#define SCAN_CHUNK   ((N_NODES + SCAN_THREADS - 1) / SCAN_THREADS)   // 98

__global__ void __launch_bounds__(SCAN_THREADS) scan_kernel() {
    __shared__ int sums[SCAN_THREADS];
    const int t     = threadIdx.x;
    const int start = t * SCAN_CHUNK;
    const int end   = min(start + SCAN_CHUNK, N_NODES);

    int s = 0;
    for (int i = start; i < end; i++) s += g_cnt[i];
    sums[t] = s;
    __syncthreads();

    // Hillis-Steele inclusive scan over 1024 partials
    for (int d = 1; d < SCAN_THREADS; d <<= 1) {
        int v = 0;
        if (t >= d) v = sums[t - d];
        __syncthreads();
        if (t >= d) sums[t] += v;
        __syncthreads();
    }

    int run = sums[t] - s;          // exclusive prefix for this chunk
    for (int i = start; i < end; i++) {
        g_off[i] = run;
        run += g_cnt[i];
    }
}

// ---------------------------------------------------------------------------
// Kernel D: scatter edges into row-sorted order
// ---------------------------------------------------------------------------
__global__ void __launch_bounds__(256) sort_scatter_kernel(const int* __restrict__ erow,
                                                           const int* __restrict__ ecol,
                                                           const float* __restrict__ eval) {
    int i = blockIdx.x * blockDim.x + threadIdx.x;
    if (i >= N_EDGES) return;
    int r   = erow[i];
    int idx = atomicAdd(&g_cur[r], 1);
    int p   = g_off[r] + idx;
    g_colS[p] = ecol[i];
    g_valS[p] = eval[i];
}

// ---------------------------------------------------------------------------
// Kernel E: Y = X @ W^T   (M=100000, N=256, K=256, fp32, NT layout)
// Block tile 128x64, K-tile 16, 256 threads, 8x4 outputs/thread.
// ---------------------------------------------------------------------------
#define BM 128
#define BN 64
#define BK 16
#define TM 8
#define TN 4

__global__ void __launch_bounds__(256) gemm_xwt_kernel(const float* __restrict__ X,
                                                       const float* __restrict__ W,
                                                       int M) {
    __shared__ float Xs[BK][BM + 4];
    __shared__ float Ws[BK][BN + 4];

    const int bm0 = blockIdx.y * BM;
    const int bn0 = blockIdx.x * BN;
    const int tid = threadIdx.x;
    const int tx  = tid & 15;
    const int ty  = tid >> 4;

    float acc[TM][TN];
#pragma unroll
    for (int m = 0; m < TM; m++)
#pragma unroll
        for (int n = 0; n < TN; n++) acc[m][n] = 0.0f;

    for (int kk = 0; kk < DIM; kk += BK) {
#pragma unroll
        for (int j = 0; j < 2; j++) {
            int i  = tid + 256 * j;
            int r  = i >> 2;
            int kq = i & 3;
            int gm = bm0 + r;
            float4 v = make_float4(0.f, 0.f, 0.f, 0.f);
            if (gm < M)
                v = *reinterpret_cast<const float4*>(X + (size_t)gm * DIM + kk + kq * 4);
            Xs[kq * 4 + 0][r] = v.x;
            Xs[kq * 4 + 1][r] = v.y;
            Xs[kq * 4 + 2][r] = v.z;
            Xs[kq * 4 + 3][r] = v.w;
        }
        {
            int r  = tid >> 2;
            int kq = tid & 3;
            float4 v = *reinterpret_cast<const float4*>(W + (size_t)(bn0 + r) * DIM + kk + kq * 4);
            Ws[kq * 4 + 0][r] = v.x;
            Ws[kq * 4 + 1][r] = v.y;
            Ws[kq * 4 + 2][r] = v.z;
            Ws[kq * 4 + 3][r] = v.w;
        }
        __syncthreads();

#pragma unroll
        for (int k = 0; k < BK; k++) {
            const float4* xr = reinterpret_cast<const float4*>(&Xs[k][ty * TM]);
            float4 a0 = xr[0];
            float4 a1 = xr[1];
            const float4* wr = reinterpret_cast<const float4*>(&Ws[k][tx * TN]);
            float4 bb = wr[0];
            float a[TM] = {a0.x, a0.y, a0.z, a0.w, a1.x, a1.y, a1.z, a1.w};
            float bv[TN] = {bb.x, bb.y, bb.z, bb.w};
#pragma unroll
            for (int m = 0; m < TM; m++)
#pragma unroll
                for (int n = 0; n < TN; n++)
                    acc[m][n] = fmaf(a[m], bv[n], acc[m][n]);
        }
        __syncthreads();
    }

#pragma unroll
    for (int m = 0; m < TM; m++) {
        int gm = bm0 + ty * TM + m;
        if (gm < M) {
            float4 v = make_float4(acc[m][0], acc[m][1], acc[m][2], acc[m][3]);
            *reinterpret_cast<float4*>(g_Y + (size_t)gm * DIM + bn0 + tx * TN) = v;
        }
    }
}

// ---------------------------------------------------------------------------
// Kernel F: per-node gather-reduce (no atomics).
// One warp per node. Each lane owns 8 floats (2x float4) of the 256-wide row.
//   out[n, :] = b[:] + sum_{e in node n} val[e] * Y[col[e], :]
// ---------------------------------------------------------------------------
__global__ void __launch_bounds__(256) gather_reduce_kernel(const float* __restrict__ b,
                                                            float* __restrict__ out) {
    const int warp = (blockIdx.x * blockDim.x + threadIdx.x) >> 5;
    const int lane = threadIdx.x & 31;
    if (warp >= N_NODES) return;

    const int start = g_off[warp];
    const int deg   = g_cnt[warp];

    float4 acc0 = make_float4(0.f, 0.f, 0.f, 0.f);
    float4 acc1 = make_float4(0.f, 0.f, 0.f, 0.f);

    for (int base = 0; base < deg; base += 32) {
        const int rem = deg - base;
        const int lim = rem < 32 ? rem : 32;
        int   c = 0;
        float v = 0.f;
        if (lane < lim) {
            c = g_colS[start + base + lane];
            v = g_valS[start + base + lane];
        }
#pragma unroll 4
        for (int j = 0; j < lim; j++) {
            const int   cc = __shfl_sync(0xffffffffu, c, j);
            const float vv = __shfl_sync(0xffffffffu, v, j);
            const float4* src = reinterpret_cast<const float4*>(g_Y + (size_t)cc * DIM);
            float4 y0 = src[lane * 2];
            float4 y1 = src[lane * 2 + 1];
            acc0.x = fmaf(vv, y0.x, acc0.x);
            acc0.y = fmaf(vv, y0.y, acc0.y);
            acc0.z = fmaf(vv, y0.z, acc0.z);
            acc0.w = fmaf(vv, y0.w, acc0.w);
            acc1.x = fmaf(vv, y1.x, acc1.x);
            acc1.y = fmaf(vv, y1.y, acc1.y);
            acc1.z = fmaf(vv, y1.z, acc1.z);
            acc1.w = fmaf(vv, y1.w, acc1.w);
        }
    }

    const float4* bv = reinterpret_cast<const float4*>(b);
    float4 b0 = bv[lane * 2];
    float4 b1 = bv[lane * 2 + 1];
    acc0.x += b0.x; acc0.y += b0.y; acc0.z += b0.z; acc0.w += b0.w;
    acc1.x += b1.x; acc1.y += b1.y; acc1.z += b1.z; acc1.w += b1.w;

    float4* dst = reinterpret_cast<float4*>(out + (size_t)warp * DIM);
    dst[lane * 2]     = acc0;
    dst[lane * 2 + 1] = acc1;
}

// ---------------------------------------------------------------------------
// Launch: inputs in metadata order: X, edge_row, edge_col, edge_val, W, b
// ---------------------------------------------------------------------------
extern "C" void kernel_launch(void* const* d_in, const int* in_sizes, int n_in,
                              void* d_out, int out_size) {
    const float* X    = (const float*)d_in[0];
    const int*   erow = (const int*)  d_in[1];
    const int*   ecol = (const int*)  d_in[2];
    const float* eval = (const float*)d_in[3];
    const float* W    = (const float*)d_in[4];
    const float* b    = (const float*)d_in[5];
    float*       out  = (float*)d_out;

    // 1) counting sort of edges by destination row
    zero_kernel<<<(N_NODES + 255) / 256, 256>>>();
    hist_kernel<<<(N_EDGES + 255) / 256, 256>>>(erow);
    scan_kernel<<<1, SCAN_THREADS>>>();
    sort_scatter_kernel<<<(N_EDGES + 255) / 256, 256>>>(erow, ecol, eval);

    // 2) Y = X @ W^T  (independent of the sort until F)
    {
        dim3 grid(DIM / BN, (N_NODES + BM - 1) / BM);
        gemm_xwt_kernel<<<grid, 256>>>(X, W, N_NODES);
    }

    // 3) out[n] = b + sum val * Y[col]   (atomic-free)
    {
        int warps_per_block = 256 / 32;
        int blocks = (N_NODES + warps_per_block - 1) / warps_per_block;
        gather_reduce_kernel<<<blocks, 256>>>(b, out);
    }
}

// round 5
// speedup vs baseline: 1.8547x; 1.2154x over previous
#include <cuda_runtime.h>
#include <cuda_fp16.h>
#include <cstdint>

#define N_NODES 100000
#define N_EDGES 3200000
#define DIM     256

// ---------------------------------------------------------------------------
// Static device scratch (no runtime allocation allowed)
// ---------------------------------------------------------------------------
__device__ __half2 g_Yh[(size_t)N_NODES * (DIM / 2)];  // X @ W^T in fp16 (51.2 MB)
__device__ int   g_colS[N_EDGES];                      // sorted edge cols
__device__ float g_valS[N_EDGES];                      // sorted edge vals
__device__ int   g_cnt[N_NODES];                       // per-row degree
__device__ int   g_off[N_NODES];                       // exclusive prefix
__device__ int   g_cur[N_NODES];                       // scatter cursor

// ---------------------------------------------------------------------------
// Kernel A: zero counters + cursors
// ---------------------------------------------------------------------------
__global__ void __launch_bounds__(256) zero_kernel() {
    int i = blockIdx.x * blockDim.x + threadIdx.x;
    if (i < N_NODES) { g_cnt[i] = 0; g_cur[i] = 0; }
}

// ---------------------------------------------------------------------------
// Kernel B: histogram of edge destination rows
// ---------------------------------------------------------------------------
__global__ void __launch_bounds__(256) hist_kernel(const int* __restrict__ erow) {
    int i = blockIdx.x * blockDim.x + threadIdx.x;
    if (i < N_EDGES) atomicAdd(&g_cnt[erow[i]], 1);
}

// ---------------------------------------------------------------------------
// Kernel C: single-block chunked exclusive scan of g_cnt -> g_off
// ---------------------------------------------------------------------------
#define SCAN_THREADS 1024
#define SCAN_CHUNK   ((N_NODES + SCAN_THREADS - 1) / SCAN_THREADS)   // 98

__global__ void __launch_bounds__(SCAN_THREADS) scan_kernel() {
    __shared__ int sums[SCAN_THREADS];
    const int t     = threadIdx.x;
    const int start = t * SCAN_CHUNK;
    const int end   = min(start + SCAN_CHUNK, N_NODES);

    int s = 0;
    for (int i = start; i < end; i++) s += g_cnt[i];
    sums[t] = s;
    __syncthreads();

    for (int d = 1; d < SCAN_THREADS; d <<= 1) {
        int v = 0;
        if (t >= d) v = sums[t - d];
        __syncthreads();
        if (t >= d) sums[t] += v;
        __syncthreads();
    }

    int run = sums[t] - s;
    for (int i = start; i < end; i++) {
        g_off[i] = run;
        run += g_cnt[i];
    }
}

// ---------------------------------------------------------------------------
// Kernel D: scatter edges into row-sorted order
// ---------------------------------------------------------------------------
__global__ void __launch_bounds__(256) sort_scatter_kernel(const int* __restrict__ erow,
                                                           const int* __restrict__ ecol,
                                                           const float* __restrict__ eval) {
    int i = blockIdx.x * blockDim.x + threadIdx.x;
    if (i >= N_EDGES) return;
    int r   = erow[i];
    int idx = atomicAdd(&g_cur[r], 1);
    int p   = g_off[r] + idx;
    g_colS[p] = ecol[i];
    g_valS[p] = eval[i];
}

// ---------------------------------------------------------------------------
// Kernel E: Y = X @ W^T, fp32 compute, fp16 store.
// Block tile 128x64, K-tile 16, 256 threads, 8x4 outputs/thread.
// ---------------------------------------------------------------------------
#define BM 128
#define BN 64
#define BK 16
#define TM 8
#define TN 4

__global__ void __launch_bounds__(256) gemm_xwt_kernel(const float* __restrict__ X,
                                                       const float* __restrict__ W,
                                                       int M) {
    __shared__ float Xs[BK][BM + 4];
    __shared__ float Ws[BK][BN + 4];

    const int bm0 = blockIdx.y * BM;
    const int bn0 = blockIdx.x * BN;
    const int tid = threadIdx.x;
    const int tx  = tid & 15;
    const int ty  = tid >> 4;

    float acc[TM][TN];
#pragma unroll
    for (int m = 0; m < TM; m++)
#pragma unroll
        for (int n = 0; n < TN; n++) acc[m][n] = 0.0f;

    for (int kk = 0; kk < DIM; kk += BK) {
#pragma unroll
        for (int j = 0; j < 2; j++) {
            int i  = tid + 256 * j;
            int r  = i >> 2;
            int kq = i & 3;
            int gm = bm0 + r;
            float4 v = make_float4(0.f, 0.f, 0.f, 0.f);
            if (gm < M)
                v = *reinterpret_cast<const float4*>(X + (size_t)gm * DIM + kk + kq * 4);
            Xs[kq * 4 + 0][r] = v.x;
            Xs[kq * 4 + 1][r] = v.y;
            Xs[kq * 4 + 2][r] = v.z;
            Xs[kq * 4 + 3][r] = v.w;
        }
        {
            int r  = tid >> 2;
            int kq = tid & 3;
            float4 v = *reinterpret_cast<const float4*>(W + (size_t)(bn0 + r) * DIM + kk + kq * 4);
            Ws[kq * 4 + 0][r] = v.x;
            Ws[kq * 4 + 1][r] = v.y;
            Ws[kq * 4 + 2][r] = v.z;
            Ws[kq * 4 + 3][r] = v.w;
        }
        __syncthreads();

#pragma unroll
        for (int k = 0; k < BK; k++) {
            const float4* xr = reinterpret_cast<const float4*>(&Xs[k][ty * TM]);
            float4 a0 = xr[0];
            float4 a1 = xr[1];
            const float4* wr = reinterpret_cast<const float4*>(&Ws[k][tx * TN]);
            float4 bb = wr[0];
            float a[TM] = {a0.x, a0.y, a0.z, a0.w, a1.x, a1.y, a1.z, a1.w};
            float bv[TN] = {bb.x, bb.y, bb.z, bb.w};
#pragma unroll
            for (int m = 0; m < TM; m++)
#pragma unroll
                for (int n = 0; n < TN; n++)
                    acc[m][n] = fmaf(a[m], bv[n], acc[m][n]);
        }
        __syncthreads();
    }

    // Store as fp16: 4 floats -> 2 half2 = one 8B store
#pragma unroll
    for (int m = 0; m < TM; m++) {
        int gm = bm0 + ty * TM + m;
        if (gm < M) {
            __half2 h0 = __floats2half2_rn(acc[m][0], acc[m][1]);
            __half2 h1 = __floats2half2_rn(acc[m][2], acc[m][3]);
            __half2* dst = g_Yh + (size_t)gm * (DIM / 2) + (bn0 >> 1) + tx * 2;
            dst[0] = h0;
            dst[1] = h1;
        }
    }
}

// ---------------------------------------------------------------------------
// Kernel F: per-node gather-reduce (no atomics), fp16 gather, fp32 accum.
// One warp per node; each lane owns 8 floats (= one uint4 of 8 halves).
// ---------------------------------------------------------------------------
__global__ void __launch_bounds__(256) gather_reduce_kernel(const float* __restrict__ b,
                                                            float* __restrict__ out) {
    const int warp = (blockIdx.x * blockDim.x + threadIdx.x) >> 5;
    const int lane = threadIdx.x & 31;
    if (warp >= N_NODES) return;

    const int start = g_off[warp];
    const int deg   = g_cnt[warp];

    float acc[8] = {0.f, 0.f, 0.f, 0.f, 0.f, 0.f, 0.f, 0.f};

    for (int base = 0; base < deg; base += 32) {
        const int rem = deg - base;
        const int lim = rem < 32 ? rem : 32;
        int   c = 0;
        float v = 0.f;
        if (lane < lim) {
            c = g_colS[start + base + lane];
            v = g_valS[start + base + lane];
        }
#pragma unroll 4
        for (int j = 0; j < lim; j++) {
            const int   cc = __shfl_sync(0xffffffffu, c, j);
            const float vv = __shfl_sync(0xffffffffu, v, j);
            // one 16B load = 8 halves per lane
            const uint4* src = reinterpret_cast<const uint4*>(g_Yh + (size_t)cc * (DIM / 2));
            uint4 p = src[lane];
            const __half2* h = reinterpret_cast<const __half2*>(&p);
#pragma unroll
            for (int q = 0; q < 4; q++) {
                float2 f = __half22float2(h[q]);
                acc[q * 2 + 0] = fmaf(vv, f.x, acc[q * 2 + 0]);
                acc[q * 2 + 1] = fmaf(vv, f.y, acc[q * 2 + 1]);
            }
        }
    }

    const float4* bv = reinterpret_cast<const float4*>(b);
    float4 b0 = bv[lane * 2];
    float4 b1 = bv[lane * 2 + 1];
    float4 o0 = make_float4(acc[0] + b0.x, acc[1] + b0.y, acc[2] + b0.z, acc[3] + b0.w);
    float4 o1 = make_float4(acc[4] + b1.x, acc[5] + b1.y, acc[6] + b1.z, acc[7] + b1.w);

    float4* dst = reinterpret_cast<float4*>(out + (size_t)warp * DIM);
    dst[lane * 2]     = o0;
    dst[lane * 2 + 1] = o1;
}

// ---------------------------------------------------------------------------
// Launch (single stream — no stream/event APIs, minimal harness surface).
// Inputs in metadata order: X, edge_row, edge_col, edge_val, W, b
// ---------------------------------------------------------------------------
extern "C" void kernel_launch(void* const* d_in, const int* in_sizes, int n_in,
                              void* d_out, int out_size) {
    const float* X    = (const float*)d_in[0];
    const int*   erow = (const int*)  d_in[1];
    const int*   ecol = (const int*)  d_in[2];
    const float* eval = (const float*)d_in[3];
    const float* W    = (const float*)d_in[4];
    const float* b    = (const float*)d_in[5];
    float*       out  = (float*)d_out;

    // 1) counting sort of edges by destination row
    zero_kernel<<<(N_NODES + 255) / 256, 256>>>();
    hist_kernel<<<(N_EDGES + 255) / 256, 256>>>(erow);
    scan_kernel<<<1, SCAN_THREADS>>>();
    sort_scatter_kernel<<<(N_EDGES + 255) / 256, 256>>>(erow, ecol, eval);

    // 2) Y = fp16(X @ W^T)
    {
        dim3 grid(DIM / BN, (N_NODES + BM - 1) / BM);
        gemm_xwt_kernel<<<grid, 256>>>(X, W, N_NODES);
    }

    // 3) out[n] = b + sum val * Y[col]   (atomic-free)
    {
        int warps_per_block = 256 / 32;
        int blocks = (N_NODES + warps_per_block - 1) / warps_per_block;
        gather_reduce_kernel<<<blocks, 256>>>(b, out);
    }
}

// round 6
// speedup vs baseline: 3.0044x; 1.6199x over previous
#include <cuda_runtime.h>
#include <cuda_fp16.h>
#include <cstdint>

#define N_NODES 100000
#define N_EDGES 3200000
#define DIM     256

// ---------------------------------------------------------------------------
// Static device scratch (no runtime allocation allowed)
// ---------------------------------------------------------------------------
__device__ __half2 g_Yh[(size_t)N_NODES * (DIM / 2)];  // X @ W^T fp16 (51.2 MB)
__device__ uint2 g_edgeS[N_EDGES];                     // sorted (col, val) 25.6 MB
__device__ int   g_cnt[N_NODES];                       // per-row degree
__device__ int   g_off[N_NODES];                       // exclusive prefix
__device__ int   g_cur[N_NODES];                       // scatter cursor

// ---------------------------------------------------------------------------
// Kernel A: zero counters + cursors
// ---------------------------------------------------------------------------
__global__ void __launch_bounds__(256) zero_kernel() {
    int i = blockIdx.x * blockDim.x + threadIdx.x;
    if (i < N_NODES) { g_cnt[i] = 0; g_cur[i] = 0; }
}

// ---------------------------------------------------------------------------
// Kernel B: histogram of edge destination rows
// ---------------------------------------------------------------------------
__global__ void __launch_bounds__(256) hist_kernel(const int* __restrict__ erow) {
    int i = blockIdx.x * blockDim.x + threadIdx.x;
    if (i < N_EDGES) atomicAdd(&g_cnt[erow[i]], 1);
}

// ---------------------------------------------------------------------------
// Kernel C: single-block chunked exclusive scan of g_cnt -> g_off
// ---------------------------------------------------------------------------
#define SCAN_THREADS 1024
#define SCAN_CHUNK   ((N_NODES + SCAN_THREADS - 1) / SCAN_THREADS)   // 98

__global__ void __launch_bounds__(SCAN_THREADS) scan_kernel() {
    __shared__ int sums[SCAN_THREADS];
    const int t     = threadIdx.x;
    const int start = t * SCAN_CHUNK;
    const int end   = min(start + SCAN_CHUNK, N_NODES);

    int s = 0;
    for (int i = start; i < end; i++) s += g_cnt[i];
    sums[t] = s;
    __syncthreads();

    for (int d = 1; d < SCAN_THREADS; d <<= 1) {
        int v = 0;
        if (t >= d) v = sums[t - d];
        __syncthreads();
        if (t >= d) sums[t] += v;
        __syncthreads();
    }

    int run = sums[t] - s;
    for (int i = start; i < end; i++) {
        g_off[i] = run;
        run += g_cnt[i];
    }
}

// ---------------------------------------------------------------------------
// Kernel D: scatter edges into row-sorted order (packed 8B records)
// ---------------------------------------------------------------------------
__global__ void __launch_bounds__(256) sort_scatter_kernel(const int* __restrict__ erow,
                                                           const int* __restrict__ ecol,
                                                           const float* __restrict__ eval) {
    int i = blockIdx.x * blockDim.x + threadIdx.x;
    if (i >= N_EDGES) return;
    int r   = erow[i];
    int idx = atomicAdd(&g_cur[r], 1);
    int p   = g_off[r] + idx;
    g_edgeS[p] = make_uint2((unsigned)ecol[i], __float_as_uint(eval[i]));
}

// ---------------------------------------------------------------------------
// Kernel E: Y = fp16(X @ W^T) via tensor cores (mma.m16n8k16, fp32 accum).
// Block tile 128x128, K-tile 32. 8 warps: 2 (M) x 4 (N); warp tile 64x32.
// X/W converted fp32 -> fp16 during smem fill.
// ---------------------------------------------------------------------------
#define GBM 128
#define GBN 128
#define GBK 32
#define TSTR 40   // smem row stride in halves (80 B: conflict-free for ldmatrix)

__device__ __forceinline__ uint32_t smem_u32(const void* p) {
    return (uint32_t)__cvta_generic_to_shared(p);
}

__global__ void __launch_bounds__(256) gemm_tc_kernel(const float* __restrict__ X,
                                                      const float* __restrict__ W,
                                                      int M) {
    __shared__ __half As[GBM * TSTR];
    __shared__ __half Bs[GBN * TSTR];

    const int tid  = threadIdx.x;
    const int warp = tid >> 5;
    const int lane = tid & 31;
    const int wm   = warp >> 2;       // 0..1 : M position
    const int wn   = warp & 3;        // 0..3 : N position
    const int bm0  = blockIdx.y * GBM;
    const int bn0  = blockIdx.x * GBN;

    float acc[4][4][4];
#pragma unroll
    for (int mf = 0; mf < 4; mf++)
#pragma unroll
        for (int nf = 0; nf < 4; nf++)
#pragma unroll
            for (int q = 0; q < 4; q++) acc[mf][nf][q] = 0.0f;

    const int lrow = tid >> 3;        // 0..31 (row within 32-row slab)
    const int lf4  = tid & 7;         // float4 index within 32-col row

    for (int kk = 0; kk < DIM; kk += GBK) {
        // --- fill A tile (X rows, fp32 -> fp16) ---
#pragma unroll
        for (int p = 0; p < 4; p++) {
            int r  = lrow + p * 32;
            int gm = bm0 + r;
            float4 v = make_float4(0.f, 0.f, 0.f, 0.f);
            if (gm < M)
                v = *reinterpret_cast<const float4*>(X + (size_t)gm * DIM + kk + lf4 * 4);
            __half2 h0 = __floats2half2_rn(v.x, v.y);
            __half2 h1 = __floats2half2_rn(v.z, v.w);
            uint2 pk;
            pk.x = *reinterpret_cast<uint32_t*>(&h0);
            pk.y = *reinterpret_cast<uint32_t*>(&h1);
            *reinterpret_cast<uint2*>(&As[r * TSTR + lf4 * 4]) = pk;
        }
        // --- fill B tile (W rows; N=256 exact, no guard) ---
#pragma unroll
        for (int p = 0; p < 4; p++) {
            int r = lrow + p * 32;
            float4 v = *reinterpret_cast<const float4*>(W + (size_t)(bn0 + r) * DIM + kk + lf4 * 4);
            __half2 h0 = __floats2half2_rn(v.x, v.y);
            __half2 h1 = __floats2half2_rn(v.z, v.w);
            uint2 pk;
            pk.x = *reinterpret_cast<uint32_t*>(&h0);
            pk.y = *reinterpret_cast<uint32_t*>(&h1);
            *reinterpret_cast<uint2*>(&Bs[r * TSTR + lf4 * 4]) = pk;
        }
        __syncthreads();

#pragma unroll
        for (int ks = 0; ks < 2; ks++) {
            const int k0 = ks * 16;
            uint32_t a[4][4];
            uint32_t bfr[4][2];

            // A fragments: 4x (16x16), ldmatrix x4
#pragma unroll
            for (int mf = 0; mf < 4; mf++) {
                int row = wm * 64 + mf * 16 + (lane & 15);
                int col = k0 + (lane >> 4) * 8;
                uint32_t addr = smem_u32(&As[row * TSTR + col]);
                asm volatile("ldmatrix.sync.aligned.m8n8.x4.shared.b16 {%0,%1,%2,%3}, [%4];"
                             : "=r"(a[mf][0]), "=r"(a[mf][1]), "=r"(a[mf][2]), "=r"(a[mf][3])
                             : "r"(addr));
            }
            // B fragments: 4x (8x16), ldmatrix x2
#pragma unroll
            for (int nf = 0; nf < 4; nf++) {
                int row = wn * 32 + nf * 8 + (lane & 7);
                int col = k0 + ((lane >> 3) & 1) * 8;
                uint32_t addr = smem_u32(&Bs[row * TSTR + col]);
                asm volatile("ldmatrix.sync.aligned.m8n8.x2.shared.b16 {%0,%1}, [%2];"
                             : "=r"(bfr[nf][0]), "=r"(bfr[nf][1])
                             : "r"(addr));
            }
#pragma unroll
            for (int mf = 0; mf < 4; mf++)
#pragma unroll
                for (int nf = 0; nf < 4; nf++) {
                    asm volatile(
                        "mma.sync.aligned.m16n8k16.row.col.f32.f16.f16.f32 "
                        "{%0,%1,%2,%3}, {%4,%5,%6,%7}, {%8,%9}, {%0,%1,%2,%3};"
                        : "+f"(acc[mf][nf][0]), "+f"(acc[mf][nf][1]),
                          "+f"(acc[mf][nf][2]), "+f"(acc[mf][nf][3])
                        : "r"(a[mf][0]), "r"(a[mf][1]), "r"(a[mf][2]), "r"(a[mf][3]),
                          "r"(bfr[nf][0]), "r"(bfr[nf][1]));
                }
        }
        __syncthreads();
    }

    // --- store Y as fp16 ---
    // C frag: c0,c1 at (m = lane/4, n = 2*(lane%4)), c2,c3 at m+8.
    const int tr = lane >> 2;
    const int tc = lane & 3;
#pragma unroll
    for (int mf = 0; mf < 4; mf++)
#pragma unroll
        for (int nf = 0; nf < 4; nf++) {
            int col2 = (bn0 + wn * 32 + nf * 8) / 2 + tc;   // half2 index
            int r0 = bm0 + wm * 64 + mf * 16 + tr;
            if (r0 < M)
                g_Yh[(size_t)r0 * (DIM / 2) + col2] =
                    __floats2half2_rn(acc[mf][nf][0], acc[mf][nf][1]);
            int r1 = r0 + 8;
            if (r1 < M)
                g_Yh[(size_t)r1 * (DIM / 2) + col2] =
                    __floats2half2_rn(acc[mf][nf][2], acc[mf][nf][3]);
        }
}

// ---------------------------------------------------------------------------
// Kernel F: per-node gather-reduce (no atomics), fp16 gather, fp32 accum.
// One warp per node; each lane owns 8 floats (= one uint4 of 8 halves).
// ---------------------------------------------------------------------------
__global__ void __launch_bounds__(256) gather_reduce_kernel(const float* __restrict__ b,
                                                            float* __restrict__ out) {
    const int warp = (blockIdx.x * blockDim.x + threadIdx.x) >> 5;
    const int lane = threadIdx.x & 31;
    if (warp >= N_NODES) return;

    const int start = g_off[warp];
    const int deg   = g_cnt[warp];

    float acc[8] = {0.f, 0.f, 0.f, 0.f, 0.f, 0.f, 0.f, 0.f};

    for (int base = 0; base < deg; base += 32) {
        const int rem = deg - base;
        const int lim = rem < 32 ? rem : 32;
        uint2 e = make_uint2(0u, 0u);
        if (lane < lim) e = g_edgeS[start + base + lane];
#pragma unroll 4
        for (int j = 0; j < lim; j++) {
            const int   cc = (int)__shfl_sync(0xffffffffu, e.x, j);
            const float vv = __uint_as_float(__shfl_sync(0xffffffffu, e.y, j));
            const uint4* src = reinterpret_cast<const uint4*>(g_Yh + (size_t)cc * (DIM / 2));
            uint4 p = src[lane];
            const __half2* h = reinterpret_cast<const __half2*>(&p);
#pragma unroll
            for (int q = 0; q < 4; q++) {
                float2 f = __half22float2(h[q]);
                acc[q * 2 + 0] = fmaf(vv, f.x, acc[q * 2 + 0]);
                acc[q * 2 + 1] = fmaf(vv, f.y, acc[q * 2 + 1]);
            }
        }
    }

    const float4* bv = reinterpret_cast<const float4*>(b);
    float4 b0 = bv[lane * 2];
    float4 b1 = bv[lane * 2 + 1];
    float4 o0 = make_float4(acc[0] + b0.x, acc[1] + b0.y, acc[2] + b0.z, acc[3] + b0.w);
    float4 o1 = make_float4(acc[4] + b1.x, acc[5] + b1.y, acc[6] + b1.z, acc[7] + b1.w);

    float4* dst = reinterpret_cast<float4*>(out + (size_t)warp * DIM);
    dst[lane * 2]     = o0;
    dst[lane * 2 + 1] = o1;
}

// ---------------------------------------------------------------------------
// Launch (single stream). Inputs: X, edge_row, edge_col, edge_val, W, b
// ---------------------------------------------------------------------------
extern "C" void kernel_launch(void* const* d_in, const int* in_sizes, int n_in,
                              void* d_out, int out_size) {
    const float* X    = (const float*)d_in[0];
    const int*   erow = (const int*)  d_in[1];
    const int*   ecol = (const int*)  d_in[2];
    const float* eval = (const float*)d_in[3];
    const float* W    = (const float*)d_in[4];
    const float* b    = (const float*)d_in[5];
    float*       out  = (float*)d_out;

    // 1) counting sort of edges by destination row
    zero_kernel<<<(N_NODES + 255) / 256, 256>>>();
    hist_kernel<<<(N_EDGES + 255) / 256, 256>>>(erow);
    scan_kernel<<<1, SCAN_THREADS>>>();
    sort_scatter_kernel<<<(N_EDGES + 255) / 256, 256>>>(erow, ecol, eval);

    // 2) Y = fp16(X @ W^T) on tensor cores
    {
        dim3 grid(DIM / GBN, (N_NODES + GBM - 1) / GBM);
        gemm_tc_kernel<<<grid, 256>>>(X, W, N_NODES);
    }

    // 3) out[n] = b + sum val * Y[col]   (atomic-free)
    {
        int warps_per_block = 256 / 32;
        int blocks = (N_NODES + warps_per_block - 1) / warps_per_block;
        gather_reduce_kernel<<<blocks, 256>>>(b, out);
    }
}